// round 1
// baseline (speedup 1.0000x reference)
#include <cuda_runtime.h>
#include <math.h>

#define NT   384        // threads per block
#define QS   388        // qkv smem row stride (floats) — /4 odd => conflict-free float4 row reads
#define SS   50         // scores smem row stride (floats)
#define NWIN 4096       // 64 batches * 8 * 8 windows

__global__ __launch_bounds__(NT, 1)
void swin_fused(const float* __restrict__ x,
                const float* __restrict__ gamma,
                const float* __restrict__ beta,
                const float* __restrict__ wqkv,
                const float* __restrict__ bqkv,
                const float* __restrict__ wout,
                const float* __restrict__ bout,
                float* __restrict__ out)
{
    extern __shared__ float sm[];
    float* qkv = sm;                    // [49][QS]  q: cols 0..127, k: 128..255, v: 256..383
    float* buf = qkv + 49 * QS;         // [49][128] xn, later attention output
    float* sc  = buf + 49 * 128;        // [8*49][SS] scores / probs

    const int tid = threadIdx.x;
    const int w   = blockIdx.x;
    const int b   = w >> 6;
    const int wy  = (w >> 3) & 7;
    const int wx  = w & 7;

    // ---------------- load window x into buf ----------------
    for (int idx = tid; idx < 49 * 128; idx += NT) {
        int t = idx >> 7;
        int c = idx & 127;
        int i = t / 7, j = t - i * 7;
        long grow = (long)b * 3136 + (wy * 7 + i) * 56 + (wx * 7 + j);
        buf[idx] = x[grow * 128 + c];
    }
    __syncthreads();

    // ---------------- LayerNorm (warp per row) ----------------
    {
        int warp = tid >> 5, lane = tid & 31;
        float g0 = gamma[lane], g1 = gamma[lane + 32], g2 = gamma[lane + 64], g3 = gamma[lane + 96];
        float e0 = beta[lane],  e1 = beta[lane + 32],  e2 = beta[lane + 64],  e3 = beta[lane + 96];
        for (int t = warp; t < 49; t += 12) {
            float v0 = buf[t * 128 + lane];
            float v1 = buf[t * 128 + lane + 32];
            float v2 = buf[t * 128 + lane + 64];
            float v3 = buf[t * 128 + lane + 96];
            float s  = v0 + v1 + v2 + v3;
            float q2 = v0 * v0 + v1 * v1 + v2 * v2 + v3 * v3;
            #pragma unroll
            for (int o = 16; o; o >>= 1) {
                s  += __shfl_xor_sync(0xffffffffu, s,  o);
                q2 += __shfl_xor_sync(0xffffffffu, q2, o);
            }
            float mu  = s * (1.0f / 128.0f);
            float var = q2 * (1.0f / 128.0f) - mu * mu;
            float rs  = rsqrtf(var + 1e-5f);
            buf[t * 128 + lane]      = (v0 - mu) * rs * g0 + e0;
            buf[t * 128 + lane + 32] = (v1 - mu) * rs * g1 + e1;
            buf[t * 128 + lane + 64] = (v2 - mu) * rs * g2 + e2;
            buf[t * 128 + lane + 96] = (v3 - mu) * rs * g3 + e3;
        }
    }
    __syncthreads();

    // ---------------- QKV GEMM: [49x128] @ [128x384] + bias ----------------
    // thread j owns output column j for all 49 rows (w_qkv is L2-resident)
    {
        const int j = tid;
        float acc[49];
        float bj = bqkv[j];
        #pragma unroll
        for (int t = 0; t < 49; t++) acc[t] = bj;

        #pragma unroll 1
        for (int k = 0; k < 128; k += 8) {
            float wr[8];
            #pragma unroll
            for (int u = 0; u < 8; u++) wr[u] = wqkv[(k + u) * 384 + j];
            #pragma unroll
            for (int t = 0; t < 49; t++) {
                float4 a0 = *(const float4*)&buf[t * 128 + k];
                float4 a1 = *(const float4*)&buf[t * 128 + k + 4];
                float r = acc[t];
                r = fmaf(a0.x, wr[0], r); r = fmaf(a0.y, wr[1], r);
                r = fmaf(a0.z, wr[2], r); r = fmaf(a0.w, wr[3], r);
                r = fmaf(a1.x, wr[4], r); r = fmaf(a1.y, wr[5], r);
                r = fmaf(a1.z, wr[6], r); r = fmaf(a1.w, wr[7], r);
                acc[t] = r;
            }
        }
        #pragma unroll
        for (int t = 0; t < 49; t++) qkv[t * QS + j] = acc[t];
    }
    __syncthreads();

    // ---------------- scores: S[h][q][k] = (Q_h K_h^T) * 0.25 ----------------
    // task = (h, qgroup of 7, kk) : 8*7*49 = 2744 tasks
    for (int task = tid; task < 2744; task += NT) {
        int kk  = task % 49;
        int tmp = task / 49;
        int qg  = tmp % 7;
        int h   = tmp / 7;
        const float* krow = &qkv[kk * QS + 128 + h * 16];
        float4 k0 = *(const float4*)(krow);
        float4 k1 = *(const float4*)(krow + 4);
        float4 k2 = *(const float4*)(krow + 8);
        float4 k3 = *(const float4*)(krow + 12);
        #pragma unroll
        for (int qq = 0; qq < 7; qq++) {
            int q = qg * 7 + qq;
            const float* qrow = &qkv[q * QS + h * 16];
            float4 a0 = *(const float4*)(qrow);
            float4 a1 = *(const float4*)(qrow + 4);
            float4 a2 = *(const float4*)(qrow + 8);
            float4 a3 = *(const float4*)(qrow + 12);
            float s = a0.x * k0.x + a0.y * k0.y + a0.z * k0.z + a0.w * k0.w
                    + a1.x * k1.x + a1.y * k1.y + a1.z * k1.z + a1.w * k1.w
                    + a2.x * k2.x + a2.y * k2.y + a2.z * k2.z + a2.w * k2.w
                    + a3.x * k3.x + a3.y * k3.y + a3.z * k3.z + a3.w * k3.w;
            sc[(h * 49 + q) * SS + kk] = s * 0.25f;
        }
    }
    __syncthreads();

    // ---------------- softmax per (h,q) row ----------------
    for (int r = tid; r < 392; r += NT) {
        float* row = &sc[r * SS];
        float m = row[0];
        #pragma unroll 1
        for (int k = 1; k < 49; k++) m = fmaxf(m, row[k]);
        float s = 0.0f;
        #pragma unroll 1
        for (int k = 0; k < 49; k++) {
            float e = __expf(row[k] - m);
            row[k] = e;
            s += e;
        }
        float inv = 1.0f / s;
        #pragma unroll 1
        for (int k = 0; k < 49; k++) row[k] *= inv;
    }
    __syncthreads();

    // ---------------- attn = P @ V  -> buf[q][h*16+d] ----------------
    for (int r = tid; r < 392; r += NT) {
        int h = r / 49, q = r % 49;
        const float* prow = &sc[r * SS];
        float a0x=0,a0y=0,a0z=0,a0w=0, a1x=0,a1y=0,a1z=0,a1w=0;
        float a2x=0,a2y=0,a2z=0,a2w=0, a3x=0,a3y=0,a3z=0,a3w=0;
        #pragma unroll 1
        for (int kk = 0; kk < 49; kk++) {
            float p = prow[kk];
            const float* vrow = &qkv[kk * QS + 256 + h * 16];
            float4 v0 = *(const float4*)(vrow);
            float4 v1 = *(const float4*)(vrow + 4);
            float4 v2 = *(const float4*)(vrow + 8);
            float4 v3 = *(const float4*)(vrow + 12);
            a0x = fmaf(p, v0.x, a0x); a0y = fmaf(p, v0.y, a0y);
            a0z = fmaf(p, v0.z, a0z); a0w = fmaf(p, v0.w, a0w);
            a1x = fmaf(p, v1.x, a1x); a1y = fmaf(p, v1.y, a1y);
            a1z = fmaf(p, v1.z, a1z); a1w = fmaf(p, v1.w, a1w);
            a2x = fmaf(p, v2.x, a2x); a2y = fmaf(p, v2.y, a2y);
            a2z = fmaf(p, v2.z, a2z); a2w = fmaf(p, v2.w, a2w);
            a3x = fmaf(p, v3.x, a3x); a3y = fmaf(p, v3.y, a3y);
            a3z = fmaf(p, v3.z, a3z); a3w = fmaf(p, v3.w, a3w);
        }
        float* o = &buf[q * 128 + h * 16];
        o[0]=a0x; o[1]=a0y; o[2]=a0z; o[3]=a0w;
        o[4]=a1x; o[5]=a1y; o[6]=a1z; o[7]=a1w;
        o[8]=a2x; o[9]=a2y; o[10]=a2z; o[11]=a2w;
        o[12]=a3x; o[13]=a3y; o[14]=a3z; o[15]=a3w;
    }
    __syncthreads();

    // ---------------- out projection + window merge ----------------
    // thread = rg*128 + j; rg handles rows t = rg, rg+3, rg+6, ...
    {
        const int rg = tid >> 7;      // 0..2
        const int j  = tid & 127;
        float acc[17];
        float bj = bout[j];
        #pragma unroll
        for (int u = 0; u < 17; u++) acc[u] = bj;

        #pragma unroll 1
        for (int k = 0; k < 128; k += 4) {
            float w0 = wout[(k + 0) * 128 + j];
            float w1 = wout[(k + 1) * 128 + j];
            float w2 = wout[(k + 2) * 128 + j];
            float w3 = wout[(k + 3) * 128 + j];
            #pragma unroll
            for (int u = 0; u < 17; u++) {
                int t = rg + u * 3;
                if (t < 49) {
                    float4 a = *(const float4*)&buf[t * 128 + k];
                    float r = acc[u];
                    r = fmaf(a.x, w0, r); r = fmaf(a.y, w1, r);
                    r = fmaf(a.z, w2, r); r = fmaf(a.w, w3, r);
                    acc[u] = r;
                }
            }
        }
        #pragma unroll
        for (int u = 0; u < 17; u++) {
            int t = rg + u * 3;
            if (t < 49) {
                int i = t / 7, jj = t - i * 7;
                long grow = (long)b * 3136 + (wy * 7 + i) * 56 + (wx * 7 + jj);
                out[grow * 128 + j] = acc[u];
            }
        }
    }
}

extern "C" void kernel_launch(void* const* d_in, const int* in_sizes, int n_in,
                              void* d_out, int out_size)
{
    const float* x     = (const float*)d_in[0];
    const float* gam   = (const float*)d_in[1];
    const float* bet   = (const float*)d_in[2];
    const float* wqkv  = (const float*)d_in[3];
    const float* bqkv  = (const float*)d_in[4];
    const float* wout  = (const float*)d_in[5];
    const float* bout  = (const float*)d_in[6];
    float* out         = (float*)d_out;

    size_t smem = (size_t)(49 * QS + 49 * 128 + 392 * SS) * sizeof(float);  // 179536 B
    cudaFuncSetAttribute(swin_fused, cudaFuncAttributeMaxDynamicSharedMemorySize, (int)smem);
    swin_fused<<<NWIN, NT, smem>>>(x, gam, bet, wqkv, bqkv, wout, bout, out);
}

// round 2
// speedup vs baseline: 1.2948x; 1.2948x over previous
#include <cuda_runtime.h>
#include <math.h>

#define NT   672
#define NWARP 21
#define NWIN 4096

typedef unsigned long long u64t;

#define FMA2(d,a,b,c) asm("fma.rn.f32x2 %0, %1, %2, %3;" : "=l"(d) : "l"(a), "l"(b), "l"(c))
#define PK2(d,x)  { unsigned _u = __float_as_uint(x); asm("mov.b64 %0, {%1,%1};" : "=l"(d) : "r"(_u)); }
#define UNPK(lo,hi,v) { unsigned _l,_h; asm("mov.b64 {%0,%1}, %2;" : "=r"(_l),"=r"(_h) : "l"(v)); lo=__uint_as_float(_l); hi=__uint_as_float(_h); }

// smem layout (floats):
//  bufp : 56x128 pair-interleaved activations  (7168)   [pair t/2][2k + (t&1)]
//  qbuf : 49x128 Q                             (6272)
//  vbuf : 49x128 V                             (6272)
//  kt   : 8x16x64 K^T per head                 (8192)
//  sc   : 392x52 scores/probs                  (20384)
#define OFF_Q   7168
#define OFF_V   (7168+6272)
#define OFF_KT  (7168+6272+6272)
#define OFF_SC  (7168+6272+6272+8192)
#define SMEM_FLOATS (7168+6272+6272+8192+20384)

__global__ __launch_bounds__(NT, 1)
void swin_fused(const float* __restrict__ x,
                const float* __restrict__ gamma,
                const float* __restrict__ beta,
                const float* __restrict__ wqkv,
                const float* __restrict__ bqkv,
                const float* __restrict__ wout,
                const float* __restrict__ bout,
                float* __restrict__ out)
{
    extern __shared__ float sm[];
    float* bufp = sm;
    float* qbuf = sm + OFF_Q;
    float* vbuf = sm + OFF_V;
    float* kt   = sm + OFF_KT;
    float* sc   = sm + OFF_SC;

    const int tid  = threadIdx.x;
    const int warp = tid >> 5;
    const int lane = tid & 31;
    const int w    = blockIdx.x;
    const int b    = w >> 6;
    const int wy   = (w >> 3) & 7;
    const int wx   = w & 7;

    // ================= Phase 1: load + LayerNorm -> bufp (pair-interleaved) ======
    {
        float g0 = gamma[lane], g1 = gamma[lane + 32], g2 = gamma[lane + 64], g3 = gamma[lane + 96];
        float e0 = beta[lane],  e1 = beta[lane + 32],  e2 = beta[lane + 64],  e3 = beta[lane + 96];
        for (int t = warp; t < 56; t += NWARP) {
            float* rowp = bufp + (t >> 1) * 256 + (t & 1);
            if (t < 49) {
                int i = t / 7, j = t - i * 7;
                const float* xr = x + ((long)b * 3136 + (wy * 7 + i) * 56 + (wx * 7 + j)) * 128;
                float v0 = xr[lane], v1 = xr[lane + 32], v2 = xr[lane + 64], v3 = xr[lane + 96];
                float s  = v0 + v1 + v2 + v3;
                float q2 = v0 * v0 + v1 * v1 + v2 * v2 + v3 * v3;
                #pragma unroll
                for (int o = 16; o; o >>= 1) {
                    s  += __shfl_xor_sync(0xffffffffu, s,  o);
                    q2 += __shfl_xor_sync(0xffffffffu, q2, o);
                }
                float mu  = s * (1.0f / 128.0f);
                float var = q2 * (1.0f / 128.0f) - mu * mu;
                float rs  = rsqrtf(var + 1e-5f);
                rowp[2 * lane]        = (v0 - mu) * rs * g0 + e0;
                rowp[2 * (lane + 32)] = (v1 - mu) * rs * g1 + e1;
                rowp[2 * (lane + 64)] = (v2 - mu) * rs * g2 + e2;
                rowp[2 * (lane + 96)] = (v3 - mu) * rs * g3 + e3;
            } else {
                rowp[2 * lane] = 0.0f; rowp[2 * (lane + 32)] = 0.0f;
                rowp[2 * (lane + 64)] = 0.0f; rowp[2 * (lane + 96)] = 0.0f;
            }
        }
    }
    __syncthreads();

    // ================= Phase 2: QKV GEMM [56x128]@[128x384] (f32x2 row pairs) ====
    {
        const int rg = tid / 96;          // 0..6 -> rows 8rg..8rg+7 (4 pairs)
        const int cg = tid % 96;
        const int j0 = 4 * cg;            // 4 output cols
        const float* Abase = bufp + rg * 1024;   // 4 pairs * 256

        u64t acc[4][4];
        {
            float4 bq = *(const float4*)&bqkv[j0];
            u64t b0, b1, b2, b3;
            PK2(b0, bq.x); PK2(b1, bq.y); PK2(b2, bq.z); PK2(b3, bq.w);
            #pragma unroll
            for (int p = 0; p < 4; p++) { acc[p][0]=b0; acc[p][1]=b1; acc[p][2]=b2; acc[p][3]=b3; }
        }

        #pragma unroll 4
        for (int k = 0; k < 128; k++) {
            u64t a0 = *(const u64t*)(Abase +       2 * k);
            u64t a1 = *(const u64t*)(Abase + 256 + 2 * k);
            u64t a2 = *(const u64t*)(Abase + 512 + 2 * k);
            u64t a3 = *(const u64t*)(Abase + 768 + 2 * k);
            float4 wv = *(const float4*)&wqkv[k * 384 + j0];
            u64t w0, w1, w2, w3;
            PK2(w0, wv.x); PK2(w1, wv.y); PK2(w2, wv.z); PK2(w3, wv.w);
            FMA2(acc[0][0], a0, w0, acc[0][0]); FMA2(acc[0][1], a0, w1, acc[0][1]);
            FMA2(acc[0][2], a0, w2, acc[0][2]); FMA2(acc[0][3], a0, w3, acc[0][3]);
            FMA2(acc[1][0], a1, w0, acc[1][0]); FMA2(acc[1][1], a1, w1, acc[1][1]);
            FMA2(acc[1][2], a1, w2, acc[1][2]); FMA2(acc[1][3], a1, w3, acc[1][3]);
            FMA2(acc[2][0], a2, w0, acc[2][0]); FMA2(acc[2][1], a2, w1, acc[2][1]);
            FMA2(acc[2][2], a2, w2, acc[2][2]); FMA2(acc[2][3], a2, w3, acc[2][3]);
            FMA2(acc[3][0], a3, w0, acc[3][0]); FMA2(acc[3][1], a3, w1, acc[3][1]);
            FMA2(acc[3][2], a3, w2, acc[3][2]); FMA2(acc[3][3], a3, w3, acc[3][3]);
        }

        #pragma unroll
        for (int p = 0; p < 4; p++) {
            int t0 = 8 * rg + 2 * p;
            float lo[4], hi[4];
            #pragma unroll
            for (int c = 0; c < 4; c++) { UNPK(lo[c], hi[c], acc[p][c]); }
            #pragma unroll
            for (int par = 0; par < 2; par++) {
                int t = t0 + par;
                if (t < 49) {
                    float v0 = par ? hi[0] : lo[0], v1 = par ? hi[1] : lo[1];
                    float v2 = par ? hi[2] : lo[2], v3 = par ? hi[3] : lo[3];
                    if (j0 < 128) {
                        *(float4*)&qbuf[t * 128 + j0] = make_float4(v0, v1, v2, v3);
                    } else if (j0 < 256) {
                        int hh = (j0 - 128) >> 4, dd = (j0 - 128) & 15;
                        int base = (hh * 16 + dd) * 64 + t;
                        kt[base] = v0; kt[base + 64] = v1; kt[base + 128] = v2; kt[base + 192] = v3;
                    } else {
                        *(float4*)&vbuf[t * 128 + (j0 - 256)] = make_float4(v0, v1, v2, v3);
                    }
                }
            }
        }
    }
    __syncthreads();

    // ================= Phase 3: scores S = Q K^T * 0.25 ==========================
    // 200 tasks: (h, q-pair). lanes cover kk = lane and lane+32.
    for (int task = warp; task < 200; task += NWARP) {
        int h = task / 25, qp = task % 25;
        int q0 = 2 * qp;
        int q1 = (q0 + 1 < 49) ? q0 + 1 : q0;
        const float* kth = kt + h * 1024;
        const float* qr0 = qbuf + q0 * 128 + h * 16;
        const float* qr1 = qbuf + q1 * 128 + h * 16;
        float a00 = 0, a01 = 0, a10 = 0, a11 = 0;
        #pragma unroll
        for (int d = 0; d < 16; d++) {
            float kv0 = kth[d * 64 + lane];
            float kv1 = kth[d * 64 + 32 + lane];
            float qv0 = qr0[d], qv1 = qr1[d];
            a00 = fmaf(qv0, kv0, a00); a01 = fmaf(qv0, kv1, a01);
            a10 = fmaf(qv1, kv0, a10); a11 = fmaf(qv1, kv1, a11);
        }
        int base0 = (h * 49 + q0) * 52;
        sc[base0 + lane] = a00 * 0.25f;
        if (lane < 17) sc[base0 + 32 + lane] = a01 * 0.25f;
        if (q1 != q0) {
            int base1 = (h * 49 + q1) * 52;
            sc[base1 + lane] = a10 * 0.25f;
            if (lane < 17) sc[base1 + 32 + lane] = a11 * 0.25f;
        }
    }
    __syncthreads();

    // ================= Phase 4: softmax per (h,q) row ============================
    for (int r = warp; r < 392; r += NWARP) {
        float* row = sc + r * 52;
        float v1 = row[lane];
        float v2 = (lane < 17) ? row[32 + lane] : -1e30f;
        float m = fmaxf(v1, v2);
        #pragma unroll
        for (int o = 16; o; o >>= 1) m = fmaxf(m, __shfl_xor_sync(0xffffffffu, m, o));
        float e1 = __expf(v1 - m);
        float e2 = (lane < 17) ? __expf(v2 - m) : 0.0f;
        float s = e1 + e2;
        #pragma unroll
        for (int o = 16; o; o >>= 1) s += __shfl_xor_sync(0xffffffffu, s, o);
        float inv = 1.0f / s;
        row[lane] = e1 * inv;
        if (lane < 17) row[32 + lane] = e2 * inv;
    }
    __syncthreads();

    // ================= Phase 5: attn = P @ V -> bufp (interleaved) ===============
    // 50 tasks: (q-pair, half of 64 dims). lane covers d0 = half*64 + 2*lane (+1).
    for (int task = warp; task < 50; task += NWARP) {
        int qp = task >> 1, half = task & 1;
        int q0 = 2 * qp, q1 = q0 + 1;
        bool hq1 = (q1 < 49);
        int q1c = hq1 ? q1 : q0;
        int d0 = half * 64 + 2 * lane;
        int h = d0 >> 4;
        const float* scr0 = sc + (h * 49 + q0) * 52;
        const float* scr1 = sc + (h * 49 + q1c) * 52;
        u64t ac0 = 0ULL, ac1 = 0ULL;
        #pragma unroll 7
        for (int kk = 0; kk < 49; kk++) {
            u64t vv = *(const u64t*)&vbuf[kk * 128 + d0];
            u64t p0, p1;
            PK2(p0, scr0[kk]); PK2(p1, scr1[kk]);
            FMA2(ac0, p0, vv, ac0);
            FMA2(ac1, p1, vv, ac1);
        }
        float l0, h0, l1, h1;
        UNPK(l0, h0, ac0); UNPK(l1, h1, ac1);
        float* prow = bufp + qp * 256;      // pair index q0>>1 == qp
        prow[2 * d0]     = l0;              // (q0, d0)
        prow[2 * d0 + 2] = h0;              // (q0, d0+1)
        if (hq1) {
            prow[2 * d0 + 1] = l1;          // (q1, d0)
            prow[2 * d0 + 3] = h1;          // (q1, d0+1)
        }
    }
    __syncthreads();

    // ================= Phase 6: out projection + window merge ====================
    if (tid < 448) {
        const int rg = tid / 64;          // 0..6
        const int cg = tid % 64;
        const int j0 = 2 * cg;
        const float* Abase = bufp + rg * 1024;

        u64t acc[4][2];
        {
            float2 bo = *(const float2*)&bout[j0];
            u64t b0, b1; PK2(b0, bo.x); PK2(b1, bo.y);
            #pragma unroll
            for (int p = 0; p < 4; p++) { acc[p][0] = b0; acc[p][1] = b1; }
        }

        #pragma unroll 4
        for (int k = 0; k < 128; k++) {
            u64t a0 = *(const u64t*)(Abase +       2 * k);
            u64t a1 = *(const u64t*)(Abase + 256 + 2 * k);
            u64t a2 = *(const u64t*)(Abase + 512 + 2 * k);
            u64t a3 = *(const u64t*)(Abase + 768 + 2 * k);
            float2 wv = *(const float2*)&wout[k * 128 + j0];
            u64t w0, w1;
            PK2(w0, wv.x); PK2(w1, wv.y);
            FMA2(acc[0][0], a0, w0, acc[0][0]); FMA2(acc[0][1], a0, w1, acc[0][1]);
            FMA2(acc[1][0], a1, w0, acc[1][0]); FMA2(acc[1][1], a1, w1, acc[1][1]);
            FMA2(acc[2][0], a2, w0, acc[2][0]); FMA2(acc[2][1], a2, w1, acc[2][1]);
            FMA2(acc[3][0], a3, w0, acc[3][0]); FMA2(acc[3][1], a3, w1, acc[3][1]);
        }

        #pragma unroll
        for (int p = 0; p < 4; p++) {
            float lo0, hi0, lo1, hi1;
            UNPK(lo0, hi0, acc[p][0]); UNPK(lo1, hi1, acc[p][1]);
            #pragma unroll
            for (int par = 0; par < 2; par++) {
                int t = 8 * rg + 2 * p + par;
                if (t < 49) {
                    int i = t / 7, jj = t - i * 7;
                    long grow = (long)b * 3136 + (wy * 7 + i) * 56 + (wx * 7 + jj);
                    float2 v = par ? make_float2(hi0, hi1) : make_float2(lo0, lo1);
                    *(float2*)&out[grow * 128 + j0] = v;
                }
            }
        }
    }
}

extern "C" void kernel_launch(void* const* d_in, const int* in_sizes, int n_in,
                              void* d_out, int out_size)
{
    const float* x    = (const float*)d_in[0];
    const float* gam  = (const float*)d_in[1];
    const float* bet  = (const float*)d_in[2];
    const float* wqkv = (const float*)d_in[3];
    const float* bqkv = (const float*)d_in[4];
    const float* wout = (const float*)d_in[5];
    const float* bout = (const float*)d_in[6];
    float* out        = (float*)d_out;

    size_t smem = (size_t)SMEM_FLOATS * sizeof(float);   // 193152 B
    cudaFuncSetAttribute(swin_fused, cudaFuncAttributeMaxDynamicSharedMemorySize, (int)smem);
    swin_fused<<<NWIN, NT, smem>>>(x, gam, bet, wqkv, bqkv, wout, bout, out);
}

// round 4
// speedup vs baseline: 1.7506x; 1.3520x over previous
#include <cuda_runtime.h>
#include <cuda_bf16.h>
#include <stdint.h>

#define NT   512
#define NWIN 4096

typedef unsigned long long u64t;

// ---- f32x2 helpers (attention path) ----
#define FMA2(d,a,b,c) asm("fma.rn.f32x2 %0, %1, %2, %3;" : "=l"(d) : "l"(a), "l"(b), "l"(c))
#define PK2(d,x)  { unsigned _u = __float_as_uint(x); asm("mov.b64 %0, {%1,%1};" : "=l"(d) : "r"(_u)); }
#define UNPK(lo,hi,v) { unsigned _l,_h; asm("mov.b64 {%0,%1}, %2;" : "=r"(_l),"=r"(_h) : "l"(v)); lo=__uint_as_float(_l); hi=__uint_as_float(_h); }

// ---- tensor-core helpers (baseline sm_80 features: legal on plain sm_103 target) ----
#define LDM4(r, a) asm volatile("ldmatrix.sync.aligned.m8n8.x4.shared.b16 {%0,%1,%2,%3}, [%4];" \
    : "=r"((r)[0]),"=r"((r)[1]),"=r"((r)[2]),"=r"((r)[3]) : "r"(a))
#define MMA(d, a, b0v, b1v) asm volatile( \
    "mma.sync.aligned.m16n8k16.row.col.f32.bf16.bf16.f32 " \
    "{%0,%1,%2,%3}, {%4,%5,%6,%7}, {%8,%9}, {%0,%1,%2,%3};" \
    : "+f"((d)[0]),"+f"((d)[1]),"+f"((d)[2]),"+f"((d)[3]) \
    : "r"((a)[0]),"r"((a)[1]),"r"((a)[2]),"r"((a)[3]),"r"(b0v),"r"(b1v))

// ---- smem byte offsets ----
// A1 (LN out, 64x136 bf16 hi/lo)         [0, 34816)         dead after QKV
// B  (wqkv chunk, 192x136 bf16 hi/lo)    [34816, 139264)    dead after QKV; reused timeline below
// QG 49x132 f32                          [139264, 165136)
// KT 128x52 f32                          [165136, 191760)
// VG 49x132 f32                          [191760, 217632)
// SC 392x50 f32 (alias A1+B)             [0, 78400)         lives scores..PV
// A2 (attn out, 64x136 bf16 hi/lo)       [78400, 113216)    written in PV
// W  (wout, 128x136 bf16 hi/lo, alias)   [0, 69632)         loaded after PV (sc dead)
#define A1H 0
#define A1L 17408
#define BHO 34816
#define BLO 87040
#define QGO 139264
#define KTO 165136
#define VGO 191760
#define SCO 0
#define A2H 78400
#define A2L 95808
#define WHO 0
#define WLO 34816
#define SMEM_BYTES 217632

__device__ uint4 g_wq_hi[6528];   // 384 x 136 ushort, [n][k]
__device__ uint4 g_wq_lo[6528];
__device__ uint4 g_wo_hi[2176];   // 128 x 136 ushort, [n][k]
__device__ uint4 g_wo_lo[2176];

__device__ __forceinline__ void split1(float v, unsigned short &h, unsigned short &l) {
    __nv_bfloat16 bh = __float2bfloat16(v);
    float r = v - __bfloat162float(bh);
    __nv_bfloat16 bl = __float2bfloat16(r);
    h = __bfloat16_as_ushort(bh);
    l = __bfloat16_as_ushort(bl);
}

__global__ void prep_kernel(const float* __restrict__ wqkv, const float* __restrict__ wout) {
    int idx = blockIdx.x * blockDim.x + threadIdx.x;
    if (idx < 49152) {                 // wqkv [k 0..127][j 0..383] -> [j][k]
        int k = idx / 384, j = idx % 384;
        unsigned short h, l;
        split1(wqkv[idx], h, l);
        ((unsigned short*)g_wq_hi)[j * 136 + k] = h;
        ((unsigned short*)g_wq_lo)[j * 136 + k] = l;
    } else if (idx < 65536) {          // wout [k][j] -> [j][k]
        int t = idx - 49152;
        int k = t >> 7, j = t & 127;
        unsigned short h, l;
        split1(wout[t], h, l);
        ((unsigned short*)g_wo_hi)[j * 136 + k] = h;
        ((unsigned short*)g_wo_lo)[j * 136 + k] = l;
    }
}

__global__ __launch_bounds__(NT, 1)
void swin_main(const float* __restrict__ x,
               const float* __restrict__ gamma,
               const float* __restrict__ beta,
               const float* __restrict__ bqkv,
               const float* __restrict__ bout,
               float* __restrict__ out)
{
    extern __shared__ unsigned char smb[];
    const int tid  = threadIdx.x;
    const int warp = tid >> 5;
    const int lane = tid & 31;
    const int w    = blockIdx.x;
    const int b    = w >> 6;
    const int wy   = (w >> 3) & 7;
    const int wx   = w & 7;

    uint32_t sb = (uint32_t)__cvta_generic_to_shared(smb);

    float* Qg = (float*)(smb + QGO);
    float* kt = (float*)(smb + KTO);
    float* Vg = (float*)(smb + VGO);
    float* sc = (float*)(smb + SCO);

    // lane-invariant ldmatrix address pieces
    const int lrow = lane & 15;
    const int lko  = (lane >> 4) * 8;
    int bn, bk;
    if (lane < 8)       { bn = lane;       bk = 0; }
    else if (lane < 16) { bn = lane - 8;   bk = 8; }
    else if (lane < 24) { bn = lane - 8;   bk = 0; }
    else                { bn = lane - 16;  bk = 8; }

    // ================= Phase 1: load x + LayerNorm -> A1 (split bf16) =========
    {
        float2 gA = *(const float2*)&gamma[2 * lane];
        float2 gB = *(const float2*)&gamma[64 + 2 * lane];
        float2 bA = *(const float2*)&beta[2 * lane];
        float2 bB = *(const float2*)&beta[64 + 2 * lane];
        for (int t = warp; t < 49; t += 16) {
            int i = t / 7, jj = t - i * 7;
            const float* xr = x + ((long)b * 3136 + (wy * 7 + i) * 56 + (wx * 7 + jj)) * 128;
            float2 va = *(const float2*)&xr[2 * lane];
            float2 vb = *(const float2*)&xr[64 + 2 * lane];
            float s  = va.x + va.y + vb.x + vb.y;
            float q2 = va.x * va.x + va.y * va.y + vb.x * vb.x + vb.y * vb.y;
            #pragma unroll
            for (int o = 16; o; o >>= 1) {
                s  += __shfl_xor_sync(0xffffffffu, s,  o);
                q2 += __shfl_xor_sync(0xffffffffu, q2, o);
            }
            float mu  = s * (1.0f / 128.0f);
            float var = q2 * (1.0f / 128.0f) - mu * mu;
            float rs  = rsqrtf(var + 1e-5f);
            float y0 = (va.x - mu) * rs * gA.x + bA.x;
            float y1 = (va.y - mu) * rs * gA.y + bA.y;
            float y2 = (vb.x - mu) * rs * gB.x + bB.x;
            float y3 = (vb.y - mu) * rs * gB.y + bB.y;
            unsigned short h0,l0,h1,l1,h2,l2,h3,l3;
            split1(y0,h0,l0); split1(y1,h1,l1); split1(y2,h2,l2); split1(y3,h3,l3);
            unsigned* pH = (unsigned*)(smb + A1H + t * 272);
            unsigned* pL = (unsigned*)(smb + A1L + t * 272);
            pH[lane]      = (unsigned)h0 | ((unsigned)h1 << 16);
            pL[lane]      = (unsigned)l0 | ((unsigned)l1 << 16);
            pH[32 + lane] = (unsigned)h2 | ((unsigned)h3 << 16);
            pL[32 + lane] = (unsigned)l2 | ((unsigned)l3 << 16);
        }
    }
    __syncthreads();

    // ================= Phase 2: QKV GEMM (HMMA, 2 chunks of N=192) ============
    for (int c = 0; c < 2; c++) {
        {
            const uint4* sH = g_wq_hi + c * 3264;
            const uint4* sL = g_wq_lo + c * 3264;
            uint4* dH = (uint4*)(smb + BHO);
            uint4* dL = (uint4*)(smb + BLO);
            for (int i = tid; i < 3264; i += NT) { dH[i] = sH[i]; dL[i] = sL[i]; }
        }
        __syncthreads();
        if (warp < 12) {
            const int j0l = warp * 16;
            const int j0g = c * 192 + j0l;
            uint32_t aH  = sb + A1H + (lrow * 136 + lko) * 2;
            uint32_t aL  = aH + (A1L - A1H);
            uint32_t bHa = sb + BHO + ((j0l + bn) * 136 + bk) * 2;
            uint32_t bLa = bHa + (BLO - BHO);

            float acc[4][2][4];
            #pragma unroll
            for (int m = 0; m < 4; m++)
                #pragma unroll
                for (int n = 0; n < 2; n++)
                    #pragma unroll
                    for (int q = 0; q < 4; q++) acc[m][n][q] = 0.0f;

            #pragma unroll
            for (int ks = 0; ks < 8; ks++) {
                uint32_t ko = ks * 32;
                uint32_t Ah[4][4], Al[4][4], Bh[4], Bl[4];
                LDM4(Bh, bHa + ko);
                LDM4(Bl, bLa + ko);
                #pragma unroll
                for (int m = 0; m < 4; m++) {
                    LDM4(Ah[m], aH + m * 4352 + ko);
                    LDM4(Al[m], aL + m * 4352 + ko);
                }
                #pragma unroll
                for (int m = 0; m < 4; m++) {
                    MMA(acc[m][0], Ah[m], Bh[0], Bh[1]);
                    MMA(acc[m][0], Al[m], Bh[0], Bh[1]);
                    MMA(acc[m][0], Ah[m], Bl[0], Bl[1]);
                    MMA(acc[m][1], Ah[m], Bh[2], Bh[3]);
                    MMA(acc[m][1], Al[m], Bh[2], Bh[3]);
                    MMA(acc[m][1], Ah[m], Bl[2], Bl[3]);
                }
            }
            // epilogue: +bias, scatter to Qg / kt / Vg
            #pragma unroll
            for (int n = 0; n < 2; n++) {
                int j = j0g + n * 8 + (lane & 3) * 2;
                float2 bb = *(const float2*)&bqkv[j];
                #pragma unroll
                for (int m = 0; m < 4; m++) {
                    int t0 = m * 16 + (lane >> 2);
                    #pragma unroll
                    for (int hhalf = 0; hhalf < 2; hhalf++) {
                        int t = t0 + 8 * hhalf;
                        if (t < 49) {
                            float v0 = acc[m][n][2 * hhalf + 0] + bb.x;
                            float v1 = acc[m][n][2 * hhalf + 1] + bb.y;
                            if (j < 128) {
                                *(float2*)&Qg[t * 132 + j] = make_float2(v0, v1);
                            } else if (j < 256) {
                                int d = j - 128;
                                kt[d * 52 + t] = v0;
                                kt[(d + 1) * 52 + t] = v1;
                            } else {
                                *(float2*)&Vg[t * 132 + (j - 256)] = make_float2(v0, v1);
                            }
                        }
                    }
                }
            }
        }
        __syncthreads();
    }

    // ================= Phase 3: scores S = Q K^T * 0.25 =======================
    for (int task = warp; task < 200; task += 16) {
        int h = task / 25, qp = task % 25;
        int q0 = 2 * qp;
        int q1 = (q0 + 1 < 49) ? q0 + 1 : q0;
        const float* kth = kt + h * 16 * 52;
        const float* qr0 = Qg + q0 * 132 + h * 16;
        const float* qr1 = Qg + q1 * 132 + h * 16;
        int kk1 = (lane < 17) ? 32 + lane : 0;
        float a00 = 0, a01 = 0, a10 = 0, a11 = 0;
        #pragma unroll
        for (int d = 0; d < 16; d++) {
            float kv0 = kth[d * 52 + lane];
            float kv1 = kth[d * 52 + kk1];
            float qv0 = qr0[d], qv1 = qr1[d];
            a00 = fmaf(qv0, kv0, a00); a01 = fmaf(qv0, kv1, a01);
            a10 = fmaf(qv1, kv0, a10); a11 = fmaf(qv1, kv1, a11);
        }
        int base0 = (h * 49 + q0) * 50;
        sc[base0 + lane] = a00 * 0.25f;
        if (lane < 17) sc[base0 + 32 + lane] = a01 * 0.25f;
        if (q1 != q0) {
            int base1 = (h * 49 + q1) * 50;
            sc[base1 + lane] = a10 * 0.25f;
            if (lane < 17) sc[base1 + 32 + lane] = a11 * 0.25f;
        }
    }
    __syncthreads();

    // ================= Phase 4: softmax per (h,q) row =========================
    for (int r = warp; r < 392; r += 16) {
        float* row = sc + r * 50;
        float v1 = row[lane];
        float v2 = (lane < 17) ? row[32 + lane] : -1e30f;
        float m = fmaxf(v1, v2);
        #pragma unroll
        for (int o = 16; o; o >>= 1) m = fmaxf(m, __shfl_xor_sync(0xffffffffu, m, o));
        float e1 = __expf(v1 - m);
        float e2 = (lane < 17) ? __expf(v2 - m) : 0.0f;
        float s = e1 + e2;
        #pragma unroll
        for (int o = 16; o; o >>= 1) s += __shfl_xor_sync(0xffffffffu, s, o);
        float inv = 1.0f / s;
        row[lane] = e1 * inv;
        if (lane < 17) row[32 + lane] = e2 * inv;
    }
    __syncthreads();

    // ================= Phase 5: attn = P @ V -> A2 (split bf16) ===============
    for (int task = warp; task < 50; task += 16) {
        int qp = task >> 1, half = task & 1;
        int q0 = 2 * qp, q1 = q0 + 1;
        bool hq1 = (q1 < 49);
        int q1c = hq1 ? q1 : q0;
        int d0 = half * 64 + 2 * lane;
        int h = d0 >> 4;
        const float* s0 = sc + (h * 49 + q0) * 50;
        const float* s1 = sc + (h * 49 + q1c) * 50;
        u64t ac0 = 0ULL, ac1 = 0ULL;
        #pragma unroll 7
        for (int kk = 0; kk < 49; kk++) {
            u64t vv = *(const u64t*)&Vg[kk * 132 + d0];
            u64t p0, p1;
            PK2(p0, s0[kk]); PK2(p1, s1[kk]);
            FMA2(ac0, p0, vv, ac0);
            FMA2(ac1, p1, vv, ac1);
        }
        float v00, v01, v10, v11;
        UNPK(v00, v01, ac0); UNPK(v10, v11, ac1);
        unsigned short sh0, sl0, sh1, sl1;
        split1(v00, sh0, sl0); split1(v01, sh1, sl1);
        *(unsigned*)(smb + A2H + q0 * 272 + d0 * 2) = (unsigned)sh0 | ((unsigned)sh1 << 16);
        *(unsigned*)(smb + A2L + q0 * 272 + d0 * 2) = (unsigned)sl0 | ((unsigned)sl1 << 16);
        if (hq1) {
            split1(v10, sh0, sl0); split1(v11, sh1, sl1);
            *(unsigned*)(smb + A2H + q1 * 272 + d0 * 2) = (unsigned)sh0 | ((unsigned)sh1 << 16);
            *(unsigned*)(smb + A2L + q1 * 272 + d0 * 2) = (unsigned)sl0 | ((unsigned)sl1 << 16);
        }
    }
    __syncthreads();

    // ================= Phase 6: out projection (HMMA) + merge =================
    {
        uint4* dH = (uint4*)(smb + WHO);
        uint4* dL = (uint4*)(smb + WLO);
        for (int i = tid; i < 2176; i += NT) { dH[i] = g_wo_hi[i]; dL[i] = g_wo_lo[i]; }
    }
    __syncthreads();
    if (warp < 8) {
        const int wm = warp & 1;
        const int wn = warp >> 1;
        const int n0 = wn * 32;
        uint32_t aH2 = sb + A2H + ((wm * 32 + lrow) * 136 + lko) * 2;
        uint32_t aL2 = aH2 + (A2L - A2H);
        uint32_t bH0 = sb + WHO + ((n0 + bn) * 136 + bk) * 2;
        uint32_t bH1 = bH0 + 16 * 272;
        uint32_t bL0 = bH0 + (WLO - WHO);
        uint32_t bL1 = bH1 + (WLO - WHO);

        float acc[2][4][4];
        #pragma unroll
        for (int m = 0; m < 2; m++)
            #pragma unroll
            for (int n = 0; n < 4; n++)
                #pragma unroll
                for (int q = 0; q < 4; q++) acc[m][n][q] = 0.0f;

        #pragma unroll
        for (int ks = 0; ks < 8; ks++) {
            uint32_t ko = ks * 32;
            uint32_t Ah[2][4], Al[2][4], Bh[8], Bl[8];
            LDM4(Bh, bH0 + ko);
            LDM4(Bh + 4, bH1 + ko);
            LDM4(Bl, bL0 + ko);
            LDM4(Bl + 4, bL1 + ko);
            #pragma unroll
            for (int m = 0; m < 2; m++) {
                LDM4(Ah[m], aH2 + m * 4352 + ko);
                LDM4(Al[m], aL2 + m * 4352 + ko);
            }
            #pragma unroll
            for (int m = 0; m < 2; m++) {
                #pragma unroll
                for (int n = 0; n < 4; n++) {
                    MMA(acc[m][n], Ah[m], Bh[2 * n], Bh[2 * n + 1]);
                    MMA(acc[m][n], Al[m], Bh[2 * n], Bh[2 * n + 1]);
                    MMA(acc[m][n], Ah[m], Bl[2 * n], Bl[2 * n + 1]);
                }
            }
        }
        // epilogue: +bias, window-merge scatter to gmem
        #pragma unroll
        for (int n = 0; n < 4; n++) {
            int j = n0 + n * 8 + (lane & 3) * 2;
            float2 bb = *(const float2*)&bout[j];
            #pragma unroll
            for (int m = 0; m < 2; m++) {
                int t0 = wm * 32 + m * 16 + (lane >> 2);
                #pragma unroll
                for (int hhalf = 0; hhalf < 2; hhalf++) {
                    int t = t0 + 8 * hhalf;
                    if (t < 49) {
                        int i = t / 7, jj = t - i * 7;
                        long grow = (long)b * 3136 + (wy * 7 + i) * 56 + (wx * 7 + jj);
                        *(float2*)&out[grow * 128 + j] =
                            make_float2(acc[m][n][2 * hhalf + 0] + bb.x,
                                        acc[m][n][2 * hhalf + 1] + bb.y);
                    }
                }
            }
        }
    }
}

extern "C" void kernel_launch(void* const* d_in, const int* in_sizes, int n_in,
                              void* d_out, int out_size)
{
    const float* x    = (const float*)d_in[0];
    const float* gam  = (const float*)d_in[1];
    const float* bet  = (const float*)d_in[2];
    const float* wqkv = (const float*)d_in[3];
    const float* bqkv = (const float*)d_in[4];
    const float* wout = (const float*)d_in[5];
    const float* bout = (const float*)d_in[6];
    float* out        = (float*)d_out;

    prep_kernel<<<128, 512>>>(wqkv, wout);

    cudaFuncSetAttribute(swin_main, cudaFuncAttributeMaxDynamicSharedMemorySize, SMEM_BYTES);
    swin_main<<<NWIN, NT, SMEM_BYTES>>>(x, gam, bet, bqkv, bout, out);
}

// round 6
// speedup vs baseline: 3.9166x; 2.2373x over previous
#include <cuda_runtime.h>
#include <cuda_bf16.h>
#include <stdint.h>

#define NT   512
#define NWIN 4096

#define LDM4(r,a) asm volatile("ldmatrix.sync.aligned.m8n8.x4.shared.b16 {%0,%1,%2,%3}, [%4];" \
    : "=r"((r)[0]),"=r"((r)[1]),"=r"((r)[2]),"=r"((r)[3]) : "r"(a))
#define LDMT2(r,a) asm volatile("ldmatrix.sync.aligned.m8n8.x2.trans.shared.b16 {%0,%1}, [%2];" \
    : "=r"((r)[0]),"=r"((r)[1]) : "r"(a))
#define MMA(d,a,b0v,b1v) asm volatile( \
    "mma.sync.aligned.m16n8k16.row.col.f32.bf16.bf16.f32 " \
    "{%0,%1,%2,%3}, {%4,%5,%6,%7}, {%8,%9}, {%0,%1,%2,%3};" \
    : "+f"((d)[0]),"+f"((d)[1]),"+f"((d)[2]),"+f"((d)[3]) \
    : "r"((a)[0]),"r"((a)[1]),"r"((a)[2]),"r"((a)[3]),"r"(b0v),"r"(b1v))

// ---- smem layout (bytes) ----
// A1 hi/lo : 64 x 136 bf16  (LN output)       [0, 34816)     — dead after QKV MMAs
// QKV hi/lo: 64 x 392 bf16  (Q|K|V split)     [34816, 135168)
// A2 hi/lo : 64 x 136 bf16  (attn out)        aliases A1
#define A1H 0
#define A1L 17408
#define QKH 34816
#define QKL (34816 + 50176)
#define A2H 0
#define A2L 17408
#define SMEM_BYTES 135168

// pre-packed weight B-fragments: [jg(24)][ks(8)][lane(32)] for qkv, [wn(8)][ks(8)][lane(32)] for wout
__device__ uint4 g_wqf_hi[6144], g_wqf_lo[6144];
__device__ uint4 g_wof_hi[2048], g_wof_lo[2048];

__device__ __forceinline__ void packsplit(float f0, float f1, uint32_t &hi, uint32_t &lo) {
    __nv_bfloat162 h2 = __floats2bfloat162_rn(f0, f1);        // low = f0, high = f1
    float2 fb = __bfloat1622float2(h2);
    __nv_bfloat162 l2 = __floats2bfloat162_rn(f0 - fb.x, f1 - fb.y);
    hi = *reinterpret_cast<uint32_t*>(&h2);
    lo = *reinterpret_cast<uint32_t*>(&l2);
}

__global__ void prep_kernel(const float* __restrict__ wqkv, const float* __restrict__ wout) {
    int T = blockIdx.x * blockDim.x + threadIdx.x;
    int lane = T & 31;
    if (T < 6144) {                       // qkv frags: jg 0..23 (c*12+w), ks 0..7
        int ks = (T >> 5) & 7;
        int jg = T >> 8;
        int j0 = (jg / 12) * 192 + (jg % 12) * 16;
        uint32_t h[4], l[4];
        #pragma unroll
        for (int r = 0; r < 4; r++) {
            int p = r >> 1, kh = r & 1;
            int j = j0 + p * 8 + (lane >> 2);
            int k = ks * 16 + kh * 8 + 2 * (lane & 3);
            packsplit(wqkv[k * 384 + j], wqkv[(k + 1) * 384 + j], h[r], l[r]);
        }
        g_wqf_hi[T] = make_uint4(h[0], h[1], h[2], h[3]);
        g_wqf_lo[T] = make_uint4(l[0], l[1], l[2], l[3]);
    } else if (T < 8192) {                // wout frags: wn 0..7, ks 0..7
        int T2 = T - 6144;
        int ks = (T2 >> 5) & 7;
        int wn = T2 >> 8;
        int j0 = wn * 16;
        uint32_t h[4], l[4];
        #pragma unroll
        for (int r = 0; r < 4; r++) {
            int p = r >> 1, kh = r & 1;
            int j = j0 + p * 8 + (lane >> 2);
            int k = ks * 16 + kh * 8 + 2 * (lane & 3);
            packsplit(wout[k * 128 + j], wout[(k + 1) * 128 + j], h[r], l[r]);
        }
        g_wof_hi[T2] = make_uint4(h[0], h[1], h[2], h[3]);
        g_wof_lo[T2] = make_uint4(l[0], l[1], l[2], l[3]);
    }
}

__global__ __launch_bounds__(NT, 1)
void swin_main(const float* __restrict__ x,
               const float* __restrict__ gamma,
               const float* __restrict__ beta,
               const float* __restrict__ bqkv,
               const float* __restrict__ bout,
               float* __restrict__ out)
{
    extern __shared__ unsigned char smb[];
    const int tid  = threadIdx.x;
    const int warp = tid >> 5;
    const int lane = tid & 31;
    const int w    = blockIdx.x;
    const int b    = w >> 6;
    const int wy   = (w >> 3) & 7;
    const int wx   = w & 7;
    const int c0   = 2 * (lane & 3);

    uint32_t sb = (uint32_t)__cvta_generic_to_shared(smb);

    // ---------- Phase 0: zero QKV rows 49..63 (both bufs) ----------
    {
        uint4 z = make_uint4(0, 0, 0, 0);
        uint4* zh = (uint4*)(smb + QKH + 49 * 784);
        uint4* zl = (uint4*)(smb + QKL + 49 * 784);
        for (int i = tid; i < 735; i += NT) { zh[i] = z; zl[i] = z; }
    }

    // ---------- Phase 1: load x + LayerNorm -> A1 (split bf16, stride 272B) ----------
    {
        float2 gA = *(const float2*)&gamma[2 * lane];
        float2 gB = *(const float2*)&gamma[64 + 2 * lane];
        float2 bA = *(const float2*)&beta[2 * lane];
        float2 bB = *(const float2*)&beta[64 + 2 * lane];
        for (int t = warp; t < 49; t += 16) {
            int i = t / 7, jj = t - i * 7;
            const float* xr = x + ((long)b * 3136 + (wy * 7 + i) * 56 + (wx * 7 + jj)) * 128;
            float2 va = *(const float2*)&xr[2 * lane];
            float2 vb = *(const float2*)&xr[64 + 2 * lane];
            float s  = va.x + va.y + vb.x + vb.y;
            float q2 = va.x * va.x + va.y * va.y + vb.x * vb.x + vb.y * vb.y;
            #pragma unroll
            for (int o = 16; o; o >>= 1) {
                s  += __shfl_xor_sync(0xffffffffu, s,  o);
                q2 += __shfl_xor_sync(0xffffffffu, q2, o);
            }
            float mu  = s * (1.0f / 128.0f);
            float var = q2 * (1.0f / 128.0f) - mu * mu;
            float rs  = rsqrtf(var + 1e-5f);
            float y0 = (va.x - mu) * rs * gA.x + bA.x;
            float y1 = (va.y - mu) * rs * gA.y + bA.y;
            float y2 = (vb.x - mu) * rs * gB.x + bB.x;
            float y3 = (vb.y - mu) * rs * gB.y + bB.y;
            uint32_t h0, l0, h1, l1;
            packsplit(y0, y1, h0, l0);
            packsplit(y2, y3, h1, l1);
            *(uint32_t*)(smb + A1H + t * 272 + 4 * lane)       = h0;
            *(uint32_t*)(smb + A1L + t * 272 + 4 * lane)       = l0;
            *(uint32_t*)(smb + A1H + t * 272 + 128 + 4 * lane) = h1;
            *(uint32_t*)(smb + A1L + t * 272 + 128 + 4 * lane) = l1;
        }
    }
    __syncthreads();

    // ---------- Phase 2: QKV GEMM (HMMA, 24 tasks of M=64 x N=16) ----------
    for (int jg = warp; jg < 24; jg += 16) {
        int j0 = (jg / 12) * 192 + (jg % 12) * 16;
        float acc[4][2][4];
        #pragma unroll
        for (int m = 0; m < 4; m++)
            #pragma unroll
            for (int n = 0; n < 2; n++)
                #pragma unroll
                for (int q = 0; q < 4; q++) acc[m][n][q] = 0.0f;

        uint32_t aH = sb + A1H + (lane & 15) * 272 + (lane >> 4) * 16;
        uint32_t aL = aH + (A1L - A1H);
        #pragma unroll
        for (int ks = 0; ks < 8; ks++) {
            uint4 fh = g_wqf_hi[(jg * 8 + ks) * 32 + lane];
            uint4 fl = g_wqf_lo[(jg * 8 + ks) * 32 + lane];
            uint32_t Ah[4][4], Al[4][4];
            #pragma unroll
            for (int m = 0; m < 4; m++) {
                LDM4(Ah[m], aH + m * (16 * 272) + ks * 32);
                LDM4(Al[m], aL + m * (16 * 272) + ks * 32);
            }
            #pragma unroll
            for (int m = 0; m < 4; m++) {
                MMA(acc[m][0], Ah[m], fh.x, fh.y);
                MMA(acc[m][0], Al[m], fh.x, fh.y);
                MMA(acc[m][0], Ah[m], fl.x, fl.y);
                MMA(acc[m][1], Ah[m], fh.z, fh.w);
                MMA(acc[m][1], Al[m], fh.z, fh.w);
                MMA(acc[m][1], Ah[m], fl.z, fl.w);
            }
        }
        // epilogue: +bias, split-bf16 store into QKV buffer at col j (Q|K|V unified)
        #pragma unroll
        for (int n = 0; n < 2; n++) {
            int j = j0 + 8 * n + c0;
            float2 bb = *(const float2*)&bqkv[j];
            #pragma unroll
            for (int m = 0; m < 4; m++) {
                #pragma unroll
                for (int rh = 0; rh < 2; rh++) {
                    int t = 16 * m + (lane >> 2) + 8 * rh;
                    if (t < 49) {
                        uint32_t hi, lo;
                        packsplit(acc[m][n][2 * rh] + bb.x, acc[m][n][2 * rh + 1] + bb.y, hi, lo);
                        *(uint32_t*)(smb + QKH + t * 784 + j * 2) = hi;
                        *(uint32_t*)(smb + QKL + t * 784 + j * 2) = lo;
                    }
                }
            }
        }
    }
    __syncthreads();

    // ---------- Phase 3: attention fully on HMMA (warp = (head, m-half)) ----------
    {
        const int h  = warp >> 1;
        const int mh = warp & 1;

        float S[2][8][4];
        #pragma unroll
        for (int m = 0; m < 2; m++)
            #pragma unroll
            for (int n = 0; n < 8; n++)
                #pragma unroll
                for (int q = 0; q < 4; q++) S[m][n][q] = 0.0f;

        // S = Q K^T  (3 split terms)
        uint32_t aQH = sb + QKH + (mh * 32 + (lane & 15)) * 784 + h * 32 + (lane >> 4) * 16;
        uint32_t aQL = aQH + (QKL - QKH);
        uint32_t aKH = sb + QKH + ((lane & 7) + ((lane & 16) >> 1)) * 784 + 256 + h * 32 + ((lane >> 3) & 1) * 16;
        uint32_t aKL = aKH + (QKL - QKH);
        #pragma unroll
        for (int term = 0; term < 3; term++) {
            uint32_t aQ = (term == 1) ? aQL : aQH;
            uint32_t aK = (term == 2) ? aKL : aKH;
            uint32_t Aq[2][4];
            LDM4(Aq[0], aQ);
            LDM4(Aq[1], aQ + 16 * 784);
            #pragma unroll
            for (int p = 0; p < 4; p++) {
                uint32_t Bk[4];
                LDM4(Bk, aK + p * (16 * 784));
                MMA(S[0][2 * p],     Aq[0], Bk[0], Bk[1]);
                MMA(S[0][2 * p + 1], Aq[0], Bk[2], Bk[3]);
                MMA(S[1][2 * p],     Aq[1], Bk[0], Bk[1]);
                MMA(S[1][2 * p + 1], Aq[1], Bk[2], Bk[3]);
            }
        }

        // softmax in registers (scale 0.25 inside exp); mask cols >= 49
        #pragma unroll
        for (int m = 0; m < 2; m++) {
            #pragma unroll
            for (int rh = 0; rh < 2; rh++) {
                float mx = -1e30f;
                #pragma unroll
                for (int n = 0; n < 8; n++) {
                    int col = 8 * n + c0;
                    if (col < 49)     mx = fmaxf(mx, S[m][n][2 * rh]);
                    if (col + 1 < 49) mx = fmaxf(mx, S[m][n][2 * rh + 1]);
                }
                mx = fmaxf(mx, __shfl_xor_sync(0xffffffffu, mx, 1));
                mx = fmaxf(mx, __shfl_xor_sync(0xffffffffu, mx, 2));
                float sum = 0.0f;
                #pragma unroll
                for (int n = 0; n < 8; n++) {
                    int col = 8 * n + c0;
                    float e0 = (col < 49)     ? __expf((S[m][n][2 * rh]     - mx) * 0.25f) : 0.0f;
                    float e1 = (col + 1 < 49) ? __expf((S[m][n][2 * rh + 1] - mx) * 0.25f) : 0.0f;
                    S[m][n][2 * rh] = e0;
                    S[m][n][2 * rh + 1] = e1;
                    sum += e0 + e1;
                }
                sum += __shfl_xor_sync(0xffffffffu, sum, 1);
                sum += __shfl_xor_sync(0xffffffffu, sum, 2);
                float inv = 1.0f / sum;
                #pragma unroll
                for (int n = 0; n < 8; n++) {
                    S[m][n][2 * rh]     *= inv;
                    S[m][n][2 * rh + 1] *= inv;
                }
            }
        }

        // O = P V  (P split from S regs; V split from smem via ldmatrix.trans)
        float O[2][2][4];
        #pragma unroll
        for (int m = 0; m < 2; m++)
            #pragma unroll
            for (int n = 0; n < 2; n++)
                #pragma unroll
                for (int q = 0; q < 4; q++) O[m][n][q] = 0.0f;

        #pragma unroll
        for (int ks = 0; ks < 4; ks++) {
            uint32_t PAh[2][4], PAl[2][4];
            #pragma unroll
            for (int m = 0; m < 2; m++) {
                packsplit(S[m][2 * ks][0],     S[m][2 * ks][1],     PAh[m][0], PAl[m][0]);
                packsplit(S[m][2 * ks][2],     S[m][2 * ks][3],     PAh[m][1], PAl[m][1]);
                packsplit(S[m][2 * ks + 1][0], S[m][2 * ks + 1][1], PAh[m][2], PAl[m][2]);
                packsplit(S[m][2 * ks + 1][2], S[m][2 * ks + 1][3], PAh[m][3], PAl[m][3]);
            }
            uint32_t vb = sb + QKH + (16 * ks + (lane & 15)) * 784 + 512 + h * 32;
            #pragma unroll
            for (int n = 0; n < 2; n++) {
                uint32_t Vh[2], Vl[2];
                LDMT2(Vh, vb + n * 16);
                LDMT2(Vl, vb + n * 16 + (QKL - QKH));
                #pragma unroll
                for (int m = 0; m < 2; m++) {
                    MMA(O[m][n], PAh[m], Vh[0], Vh[1]);
                    MMA(O[m][n], PAl[m], Vh[0], Vh[1]);
                    MMA(O[m][n], PAh[m], Vl[0], Vl[1]);
                }
            }
        }

        // epilogue: split-bf16 -> A2
        #pragma unroll
        for (int m = 0; m < 2; m++) {
            #pragma unroll
            for (int n = 0; n < 2; n++) {
                int colb = (h * 16 + 8 * n + c0) * 2;
                #pragma unroll
                for (int rh = 0; rh < 2; rh++) {
                    int t = mh * 32 + 16 * m + (lane >> 2) + 8 * rh;
                    if (t < 49) {
                        uint32_t hi, lo;
                        packsplit(O[m][n][2 * rh], O[m][n][2 * rh + 1], hi, lo);
                        *(uint32_t*)(smb + A2H + t * 272 + colb) = hi;
                        *(uint32_t*)(smb + A2L + t * 272 + colb) = lo;
                    }
                }
            }
        }
    }
    __syncthreads();

    // ---------- Phase 4: out projection (HMMA) + window merge ----------
    if (warp < 8) {
        int j0 = warp * 16;
        float acc[4][2][4];
        #pragma unroll
        for (int m = 0; m < 4; m++)
            #pragma unroll
            for (int n = 0; n < 2; n++)
                #pragma unroll
                for (int q = 0; q < 4; q++) acc[m][n][q] = 0.0f;

        uint32_t aH = sb + A2H + (lane & 15) * 272 + (lane >> 4) * 16;
        uint32_t aL = aH + (A2L - A2H);
        #pragma unroll
        for (int ks = 0; ks < 8; ks++) {
            uint4 fh = g_wof_hi[(warp * 8 + ks) * 32 + lane];
            uint4 fl = g_wof_lo[(warp * 8 + ks) * 32 + lane];
            uint32_t Ah[4][4], Al[4][4];
            #pragma unroll
            for (int m = 0; m < 4; m++) {
                LDM4(Ah[m], aH + m * (16 * 272) + ks * 32);
                LDM4(Al[m], aL + m * (16 * 272) + ks * 32);
            }
            #pragma unroll
            for (int m = 0; m < 4; m++) {
                MMA(acc[m][0], Ah[m], fh.x, fh.y);
                MMA(acc[m][0], Al[m], fh.x, fh.y);
                MMA(acc[m][0], Ah[m], fl.x, fl.y);
                MMA(acc[m][1], Ah[m], fh.z, fh.w);
                MMA(acc[m][1], Al[m], fh.z, fh.w);
                MMA(acc[m][1], Ah[m], fl.z, fl.w);
            }
        }
        #pragma unroll
        for (int n = 0; n < 2; n++) {
            int j = j0 + 8 * n + c0;
            float2 bb = *(const float2*)&bout[j];
            #pragma unroll
            for (int m = 0; m < 4; m++) {
                #pragma unroll
                for (int rh = 0; rh < 2; rh++) {
                    int t = 16 * m + (lane >> 2) + 8 * rh;
                    if (t < 49) {
                        int i = t / 7, jj = t - i * 7;
                        long grow = (long)b * 3136 + (wy * 7 + i) * 56 + (wx * 7 + jj);
                        *(float2*)&out[grow * 128 + j] =
                            make_float2(acc[m][n][2 * rh] + bb.x, acc[m][n][2 * rh + 1] + bb.y);
                    }
                }
            }
        }
    }
}

extern "C" void kernel_launch(void* const* d_in, const int* in_sizes, int n_in,
                              void* d_out, int out_size)
{
    const float* x    = (const float*)d_in[0];
    const float* gam  = (const float*)d_in[1];
    const float* bet  = (const float*)d_in[2];
    const float* wqkv = (const float*)d_in[3];
    const float* bqkv = (const float*)d_in[4];
    const float* wout = (const float*)d_in[5];
    const float* bout = (const float*)d_in[6];
    float* out        = (float*)d_out;

    prep_kernel<<<16, 512>>>(wqkv, wout);

    cudaFuncSetAttribute(swin_main, cudaFuncAttributeMaxDynamicSharedMemorySize, SMEM_BYTES);
    swin_main<<<NWIN, NT, SMEM_BYTES>>>(x, gam, bet, bqkv, bout, out);
}